// round 12
// baseline (speedup 1.0000x reference)
#include <cuda_runtime.h>
#include <cuda_fp16.h>
#include <cstdint>
#include <cstddef>

// Persistent 1-term fp16 HMMA LSTM. 128 CTAs x 512 threads, warp tile 16x32.
// R12: fused phases (enc L1(t)+L0(t+1); dec L1d(s)+deferred L0d(s+1)) +
// per-M-tile split grid barriers. Chunk engine identical to R11.
#define Bsz 256
#define Hdim 1024
#define Tlen 336
#define OUTLEN 96
#define BH (Bsz*Hdim)
#define NCTA 128
#define NTHR 512
#define ASTR 272                  // padded smem row stride for 256B rows
#define OFF_B 34816               // A: 128 rows * 272
#define STG 52224                 // + W: 64 rows * 272
#define NSTG 4
#define SMEM_TOTAL (NSTG*STG + 512)   // + xts[128] floats

__device__ __align__(16) __half g_W[6][4096 * 1024];    // gate-permuted [col][k]
__device__ __align__(16) __half g_A[2][2][BH];          // h state fp16 [layer][ping][m][k]
__device__ float g_c0[BH], g_c1[BH], g_h1f[BH], g_xt[Bsz];
__device__ unsigned g_bar[3][64];   // [id][0]=cnt, [id][32]=gen; id 0/1 = M-half, 2 = full

__device__ __forceinline__ uint32_t smem_u32(const void* p) {
    uint32_t a;
    asm("{ .reg .u64 t; cvta.to.shared.u64 t, %1; cvt.u32.u64 %0, t; }" : "=r"(a) : "l"(p));
    return a;
}
__device__ __forceinline__ void cpa16(uint32_t d, const void* s) {
    asm volatile("cp.async.cg.shared.global [%0], [%1], 16;" :: "r"(d), "l"(s));
}
__device__ __forceinline__ void cp_commit() { asm volatile("cp.async.commit_group;" ::: "memory"); }
template <int N> __device__ __forceinline__ void cp_wait() {
    asm volatile("cp.async.wait_group %0;" :: "n"(N) : "memory");
}
__device__ __forceinline__ void ldm4(uint32_t* r, uint32_t a) {
    asm volatile("ldmatrix.sync.aligned.m8n8.x4.shared.b16 {%0,%1,%2,%3}, [%4];"
        : "=r"(r[0]), "=r"(r[1]), "=r"(r[2]), "=r"(r[3]) : "r"(a));
}
__device__ __forceinline__ void mma16816(float* c, const uint32_t* a, uint32_t b0, uint32_t b1) {
    asm volatile(
        "mma.sync.aligned.m16n8k16.row.col.f32.f16.f16.f32 "
        "{%0,%1,%2,%3}, {%4,%5,%6,%7}, {%8,%9}, {%0,%1,%2,%3};"
        : "+f"(c[0]), "+f"(c[1]), "+f"(c[2]), "+f"(c[3])
        : "r"(a[0]), "r"(a[1]), "r"(a[2]), "r"(a[3]), "r"(b0), "r"(b1));
}
__device__ __forceinline__ float sigmoidf_(float x) { return 1.0f / (1.0f + expf(-x)); }

// Grid barrier over n CTAs (id selects an independent counter/gen pair).
__device__ __forceinline__ void gsync(int id, unsigned n) {
    __syncthreads();
    if (threadIdx.x == 0) {
        __threadfence();
        unsigned g = *(volatile unsigned*)&g_bar[id][32];
        unsigned a = atomicAdd(&g_bar[id][0], 1u);
        if (a == n - 1) {
            atomicExch(&g_bar[id][0], 0u);
            __threadfence();
            atomicAdd(&g_bar[id][32], 1u);
        } else {
            while (*(volatile unsigned*)&g_bar[id][32] == g) { __nanosleep(64); }
        }
        __threadfence();
    }
    __syncthreads();
}

// Permute 6 weight matrices into fp16.
// dst col = (hid>>4)*64 + ((hid>>3)&1)*32 + gate*8 + (hid&7)
__device__ void prologue(const float* const* Ws, const float* x) {
    const int gt = blockIdx.x * NTHR + threadIdx.x;
#pragma unroll 1
    for (int mat = 0; mat < 6; mat++) {
        const float* src = Ws[mat];
#pragma unroll 1
        for (int p = gt; p < (4096 * 1024 / 2); p += NCTA * NTHR) {
            int gr = p >> 9;
            int k  = (p & 511) << 1;
            float2 v = *(const float2*)(src + (size_t)gr * 1024 + k);
            int gate = gr >> 10, hid = gr & 1023;
            size_t col = (size_t)(hid >> 4) * 64 + ((hid >> 3) & 1) * 32 + gate * 8 + (hid & 7);
            size_t off = col * 1024 + k;
            __half h0 = __float2half_rn(v.x);
            __half h1 = __float2half_rn(v.y);
            *(uint32_t*)&g_W[mat][off] = (uint32_t)__half_as_ushort(h0) | ((uint32_t)__half_as_ushort(h1) << 16);
        }
    }
    float4 zf = make_float4(0.f, 0.f, 0.f, 0.f);
    uint4 z4 = make_uint4(0, 0, 0, 0);
    for (int i = gt; i < BH / 4; i += NCTA * NTHR) {
        ((float4*)g_c0)[i] = zf;
        ((float4*)g_c1)[i] = zf;
    }
    for (int i = gt; i < BH / 8; i += NCTA * NTHR) {
        ((uint4*)g_A[0][0])[i] = z4;
        ((uint4*)g_A[1][0])[i] = z4;
    }
    if (gt < Bsz) g_xt[gt] = x[(size_t)gt * Tlen + (Tlen - 1)];
}

// MMA loop over nTot passes of 8 K=128 chunks; passes [0,nP) -> accP, rest -> accQ.
__device__ __forceinline__ void mma_loop(
    uint32_t tb,
    const __half* A0, const __half* W0,
    const __half* A1, const __half* W1,
    const __half* A2, const __half* W2,
    int nP, int nTot,
    float (&accP)[4][4], float (&accQ)[4][4])
{
    const int tid = threadIdx.x;
    const int m_t = blockIdx.x & 1;
    const int n_t = blockIdx.x >> 1;
    const int C = nTot << 3;

    const __half* Ap0 = A0 + m_t * 128 * Hdim;
    const __half* Ap1 = A1 + m_t * 128 * Hdim;
    const __half* Ap2 = A2 + m_t * 128 * Hdim;
    const __half* Wp0 = W0 + (size_t)n_t * 64 * Hdim;
    const __half* Wp1 = W1 + (size_t)n_t * 64 * Hdim;
    const __half* Wp2 = W2 + (size_t)n_t * 64 * Hdim;

    auto load_chunk = [&](int ch) {
        const int pass = ch >> 3, c = ch & 7;
        const uint32_t st = tb + (ch % NSTG) * STG;
        const __half* ab = pass == 0 ? Ap0 : (pass == 1 ? Ap1 : Ap2);
        const __half* wb = pass == 0 ? Wp0 : (pass == 1 ? Wp1 : Wp2);
        const char* a = (const char*)ab + c * 256;          // gmem row stride 2048B
        const char* w = (const char*)wb + c * 256;
#pragma unroll
        for (int i = 0; i < 4; i++) {               // A: 128 rows x 16 segs
            int idx = tid + i * NTHR;
            int row = idx >> 4, seg = idx & 15;
            cpa16(st + row * ASTR + seg * 16, a + (size_t)row * 2048 + seg * 16);
        }
#pragma unroll
        for (int i = 0; i < 2; i++) {               // W: 64 rows x 16 segs
            int idx = tid + i * NTHR;
            int row = idx >> 4, seg = idx & 15;
            cpa16(st + OFF_B + row * ASTR + seg * 16, w + (size_t)row * 2048 + seg * 16);
        }
        cp_commit();
    };

    const int lane = tid & 31, w = tid >> 5;
    const int wm = w & 7, wn = w >> 3;
    const int mat = lane >> 3, r = lane & 7;
    const uint32_t a_row  = wm * 16 + (mat & 1) * 8 + r;
    const uint32_t a_koff = (mat >> 1) * 8;
    const uint32_t b_roff = wn * 32 + (mat >> 1) * 8 + r;
    const uint32_t b_koff = (mat & 1) * 8;

    load_chunk(0);
    load_chunk(1);
    load_chunk(2);

#define CHUNK_MMA(ACC)                                                                \
    _Pragma("unroll")                                                                 \
    for (int ks = 0; ks < 8; ks++) {                                                  \
        uint32_t a4[4];                                                               \
        ldm4(a4, sa + a_row * ASTR + (ks * 16 + a_koff) * 2);                         \
        _Pragma("unroll")                                                             \
        for (int q = 0; q < 2; q++) {                                                 \
            uint32_t b4[4];                                                           \
            ldm4(b4, sa + OFF_B + (q * 16 + b_roff) * ASTR + (ks * 16 + b_koff) * 2); \
            mma16816(ACC[2 * q],     a4, b4[0], b4[1]);                               \
            mma16816(ACC[2 * q + 1], a4, b4[2], b4[3]);                               \
        }                                                                             \
    }

#pragma unroll 1
    for (int ch = 0; ch < C; ch++) {
        const int rem = C - 1 - ch;
        if (rem >= 2) cp_wait<2>(); else if (rem == 1) cp_wait<1>(); else cp_wait<0>();
        __syncthreads();
        if (ch + 3 < C) load_chunk(ch + 3);
        const uint32_t sa = tb + (ch % NSTG) * STG;
        if ((ch >> 3) < nP) { CHUNK_MMA(accP) } else { CHUNK_MMA(accQ) }
    }
#undef CHUNK_MMA
}

// Pointwise LSTM epilogue: acc[j] = gate j; thread owns 2 rows x 2 hids.
__device__ __forceinline__ void lstm_epi(
    float (&acc)[4][4],
    const float* __restrict__ bias, const float* __restrict__ wih,
    const float* __restrict__ xs, int xs_stride, int xs_off,
    float* __restrict__ cst, __half* __restrict__ oA, float* __restrict__ of32)
{
    const int tid = threadIdx.x;
    const int m_t = blockIdx.x & 1;
    const int n_t = blockIdx.x >> 1;
    const int lane = tid & 31, w = tid >> 5;
    const int wm = w & 7, wn = w >> 3;
    const int grp = lane >> 2, tig = lane & 3;
    const int hid0 = n_t * 16 + wn * 8 + 2 * tig;
#pragma unroll
    for (int s = 0; s < 2; s++) {
        int mm = m_t * 128 + wm * 16 + grp + 8 * s;
        float xv = xs ? xs[(size_t)(mm - xs_off) * xs_stride] : 0.0f;
        float hn[2];
#pragma unroll
        for (int d = 0; d < 2; d++) {
            int e = 2 * s + d;
            int hd = hid0 + d;
            float pi = acc[0][e] + bias[hd]        + (wih ? xv * wih[hd]        : 0.f);
            float pf = acc[1][e] + bias[1024 + hd] + (wih ? xv * wih[1024 + hd] : 0.f);
            float pg = acc[2][e] + bias[2048 + hd] + (wih ? xv * wih[2048 + hd] : 0.f);
            float po = acc[3][e] + bias[3072 + hd] + (wih ? xv * wih[3072 + hd] : 0.f);
            size_t cix = (size_t)mm * Hdim + hd;
            float cn = sigmoidf_(pf) * cst[cix] + sigmoidf_(pi) * tanhf(pg);
            hn[d] = sigmoidf_(po) * tanhf(cn);
            cst[cix] = cn;
        }
        size_t hix = (size_t)mm * Hdim + hid0;
        __half h0 = __float2half_rn(hn[0]);
        __half h1 = __float2half_rn(hn[1]);
        *(uint32_t*)&oA[hix] = (uint32_t)__half_as_ushort(h0) | ((uint32_t)__half_as_ushort(h1) << 16);
        if (of32) *(float2*)&of32[hix] = make_float2(hn[0], hn[1]);
    }
}

__device__ __forceinline__ void zero_acc(float (&a)[4][4]) {
#pragma unroll
    for (int j = 0; j < 4; j++)
#pragma unroll
        for (int e = 0; e < 4; e++) a[j][e] = 0.0f;
}

__global__ void __launch_bounds__(NTHR, 1) lstm_mma_kernel(
    const float* __restrict__ x,
    const float* eWih0, const float* eWhh0, const float* eb0,
    const float* eWih1, const float* eWhh1, const float* eb1,
    const float* dWih0, const float* dWhh0, const float* db0,
    const float* dWih1, const float* dWhh1, const float* db1,
    const float* fcW, const float* fcb, float* __restrict__ out)
{
    extern __shared__ uint8_t dsm[];
    const uint32_t tb = smem_u32(dsm);
    float* xts = (float*)(dsm + NSTG * STG);     // per-CTA FC broadcast (128 floats)

    const int tid = threadIdx.x;
    const int m_t = blockIdx.x & 1;
    const int n_t = blockIdx.x >> 1;

    const float* Ws[6] = { eWhh0, eWih1, eWhh1, dWhh0, dWih1, dWhh1 };
    prologue(Ws, x);
    gsync(2, NCTA);                 // full barrier: weights/state visible to all

    float accP[4][4], accQ[4][4];
    int p0 = 0, p1 = 0;

    // ---- init: L0enc(0) from zero state ----
    zero_acc(accQ);
    mma_loop(tb, g_A[0][0], g_W[0], g_A[0][0], g_W[0], g_A[0][0], g_W[0], 0, 1, accP, accQ);
    lstm_epi(accQ, eb0, eWih0, x + 0, Tlen, 0, g_c0, g_A[0][1], nullptr);
    p0 = 1;
    gsync(m_t, 64);

    // ---- encoder: fused L1(t) + L0(t+1); t=335 fuses L0dec(0) ----
#pragma unroll 1
    for (int t = 0; t < Tlen; t++) {
        const bool last = (t == Tlen - 1);
        zero_acc(accP);
        zero_acc(accQ);
        mma_loop(tb, g_A[0][p0], g_W[1], g_A[1][p1], g_W[2],
                 g_A[0][p0], last ? g_W[3] : g_W[0], 2, 3, accP, accQ);
        lstm_epi(accP, eb1, nullptr, nullptr, 0, 0, g_c1, g_A[1][p1 ^ 1], nullptr);
        if (!last)
            lstm_epi(accQ, eb0, eWih0, x + (t + 1), Tlen, 0, g_c0, g_A[0][p0 ^ 1], nullptr);
        else
            lstm_epi(accQ, db0, dWih0, g_xt, 1, 0, g_c0, g_A[0][p0 ^ 1], nullptr);
        p0 ^= 1;
        p1 ^= 1;
        gsync(m_t, 64);
    }

    // ---- decoder: [L1d(s)+L0d(s+1) MMA] sync [FC + deferred L0d epilogue] ----
#pragma unroll 1
    for (int s = 0; s < OUTLEN; s++) {
        const bool lastS = (s == OUTLEN - 1);
        zero_acc(accP);
        zero_acc(accQ);
        mma_loop(tb, g_A[0][p0], g_W[4], g_A[1][p1], g_W[5],
                 g_A[0][p0], g_W[3], 2, lastS ? 2 : 3, accP, accQ);
        lstm_epi(accP, db1, nullptr, nullptr, 0, 0, g_c1, g_A[1][p1 ^ 1], g_h1f);
        p1 ^= 1;
        gsync(m_t, 64);

        // FC: each CTA computes y for its own 128 rows (4 threads/row).
        {
            const int r = tid >> 2, q4 = tid & 3;
            const int m = m_t * 128 + r;
            const float4* hr = (const float4*)(g_h1f + (size_t)m * Hdim + q4 * 256);
            const float4* wr = (const float4*)(fcW + q4 * 256);
            float sum = 0.0f;
#pragma unroll 8
            for (int i = 0; i < 64; i++) {
                float4 v = hr[i], u = wr[i];
                sum += v.x * u.x + v.y * u.y + v.z * u.z + v.w * u.w;
            }
            sum += __shfl_xor_sync(0xFFFFFFFFu, sum, 1);
            sum += __shfl_xor_sync(0xFFFFFFFFu, sum, 2);
            if (q4 == 0) {
                float y = sum + fcb[0];
                xts[r] = y;
                if (n_t == 0) out[(size_t)m * OUTLEN + s] = y;
            }
            __syncthreads();
        }
        if (!lastS) {
            lstm_epi(accQ, db0, dWih0, xts, 1, m_t * 128, g_c0, g_A[0][p0 ^ 1], nullptr);
            p0 ^= 1;
        }
        gsync(m_t, 64);
    }
}

extern "C" void kernel_launch(void* const* d_in, const int* in_sizes, int n_in,
                              void* d_out, int out_size)
{
    (void)in_sizes; (void)n_in; (void)out_size;
    cudaFuncSetAttribute(lstm_mma_kernel, cudaFuncAttributeMaxDynamicSharedMemorySize, SMEM_TOTAL);
    lstm_mma_kernel<<<NCTA, NTHR, SMEM_TOTAL>>>(
        (const float*)d_in[0],
        (const float*)d_in[1],  (const float*)d_in[2],  (const float*)d_in[3],
        (const float*)d_in[4],  (const float*)d_in[5],  (const float*)d_in[6],
        (const float*)d_in[7],  (const float*)d_in[8],  (const float*)d_in[9],
        (const float*)d_in[10], (const float*)d_in[11], (const float*)d_in[12],
        (const float*)d_in[13], (const float*)d_in[14],
        (float*)d_out);
}

// round 13
// speedup vs baseline: 1.0388x; 1.0388x over previous
#include <cuda_runtime.h>
#include <cuda_fp16.h>
#include <cstdint>
#include <cstddef>

// Persistent 1-term fp16 HMMA LSTM. 128 CTAs x 512 threads.
// R13: k-split warp tiling — 16 warps = 4 M-subtiles(32) x 2 N-halves(32) x 2 K-halves.
// Per chunk/warp: 16 ldm4 + 32 HMMA (was 24+32). Once-per-phase partner reduction.
// Phase schedule, cp.async pipeline, permuted fp16 weights identical to R11.
#define Bsz 256
#define Hdim 1024
#define Tlen 336
#define OUTLEN 96
#define BH (Bsz*Hdim)
#define NCTA 128
#define NTHR 512
#define ASTR 272                  // padded smem row stride for 256B rows
#define OFF_B 34816               // A: 128 rows * 272
#define STG 52224                 // + W: 64 rows * 272
#define NSTG 4
#define SMEM_TOTAL (NSTG*STG)     // 208896

__device__ __align__(16) __half g_W[6][4096 * 1024];    // gate-permuted [col][k]
__device__ __align__(16) __half g_A[2][2][BH];          // h state fp16 [layer][ping][m][k]
__device__ float g_c0[BH], g_c1[BH], g_h1f[BH], g_xt[Bsz];
__device__ unsigned g_cnt, g_gen;

__device__ __forceinline__ uint32_t smem_u32(const void* p) {
    uint32_t a;
    asm("{ .reg .u64 t; cvta.to.shared.u64 t, %1; cvt.u32.u64 %0, t; }" : "=r"(a) : "l"(p));
    return a;
}
__device__ __forceinline__ void cpa16(uint32_t d, const void* s) {
    asm volatile("cp.async.cg.shared.global [%0], [%1], 16;" :: "r"(d), "l"(s));
}
__device__ __forceinline__ void cp_commit() { asm volatile("cp.async.commit_group;" ::: "memory"); }
template <int N> __device__ __forceinline__ void cp_wait() {
    asm volatile("cp.async.wait_group %0;" :: "n"(N) : "memory");
}
__device__ __forceinline__ void ldm4(uint32_t* r, uint32_t a) {
    asm volatile("ldmatrix.sync.aligned.m8n8.x4.shared.b16 {%0,%1,%2,%3}, [%4];"
        : "=r"(r[0]), "=r"(r[1]), "=r"(r[2]), "=r"(r[3]) : "r"(a));
}
__device__ __forceinline__ void mma16816(float* c, const uint32_t* a, uint32_t b0, uint32_t b1) {
    asm volatile(
        "mma.sync.aligned.m16n8k16.row.col.f32.f16.f16.f32 "
        "{%0,%1,%2,%3}, {%4,%5,%6,%7}, {%8,%9}, {%0,%1,%2,%3};"
        : "+f"(c[0]), "+f"(c[1]), "+f"(c[2]), "+f"(c[3])
        : "r"(a[0]), "r"(a[1]), "r"(a[2]), "r"(a[3]), "r"(b0), "r"(b1));
}
__device__ __forceinline__ float sigmoidf_(float x) { return 1.0f / (1.0f + expf(-x)); }

__device__ __forceinline__ void grid_sync() {
    __syncthreads();
    if (threadIdx.x == 0) {
        __threadfence();
        unsigned g = *(volatile unsigned*)&g_gen;
        unsigned a = atomicAdd(&g_cnt, 1u);
        if (a == NCTA - 1) {
            atomicExch(&g_cnt, 0u);
            __threadfence();
            atomicAdd(&g_gen, 1u);
        } else {
            while (*(volatile unsigned*)&g_gen == g) { __nanosleep(64); }
        }
        __threadfence();
    }
    __syncthreads();
}

// Permute 6 weight matrices into fp16.
// dst col = (hid>>4)*64 + ((hid>>3)&1)*32 + gate*8 + (hid&7)
__device__ void prologue(const float* const* Ws, const float* x) {
    const int gt = blockIdx.x * NTHR + threadIdx.x;
#pragma unroll 1
    for (int mat = 0; mat < 6; mat++) {
        const float* src = Ws[mat];
#pragma unroll 1
        for (int p = gt; p < (4096 * 1024 / 2); p += NCTA * NTHR) {
            int gr = p >> 9;
            int k  = (p & 511) << 1;
            float2 v = *(const float2*)(src + (size_t)gr * 1024 + k);
            int gate = gr >> 10, hid = gr & 1023;
            size_t col = (size_t)(hid >> 4) * 64 + ((hid >> 3) & 1) * 32 + gate * 8 + (hid & 7);
            size_t off = col * 1024 + k;
            __half h0 = __float2half_rn(v.x);
            __half h1 = __float2half_rn(v.y);
            *(uint32_t*)&g_W[mat][off] = (uint32_t)__half_as_ushort(h0) | ((uint32_t)__half_as_ushort(h1) << 16);
        }
    }
    float4 zf = make_float4(0.f, 0.f, 0.f, 0.f);
    uint4 z4 = make_uint4(0, 0, 0, 0);
    for (int i = gt; i < BH / 4; i += NCTA * NTHR) {
        ((float4*)g_c0)[i] = zf;
        ((float4*)g_c1)[i] = zf;
    }
    for (int i = gt; i < BH / 8; i += NCTA * NTHR) {
        ((uint4*)g_A[0][0])[i] = z4;
        ((uint4*)g_A[1][0])[i] = z4;
    }
    if (gt < Bsz) g_xt[gt] = x[(size_t)gt * Tlen + (Tlen - 1)];
}

// One recurrence phase: D(128x64) = sum over passes A@W^T, fused LSTM pointwise.
// Warp wrp: M-subtile wm=wrp&3 (32 rows), N-half wn=(wrp>>2)&1 (32 cols), K-half kh=wrp>>3.
__device__ __noinline__ void lstm_phase(
    uint32_t tb, int npass,
    const __half* A0, const __half* W0,
    const __half* A1, const __half* W1,
    const float* __restrict__ bias, const float* __restrict__ wih,
    const float* __restrict__ xs, int xs_stride,
    float* __restrict__ cst,
    __half* __restrict__ oA, float* __restrict__ of32)
{
    extern __shared__ uint8_t dsm[];
    const int tid = threadIdx.x;
    const int m_t = blockIdx.x & 1;
    const int n_t = blockIdx.x >> 1;
    const int C = npass << 3;               // 8 chunks of K=128 per pass

    const __half* Ap[2] = { A0 + m_t * 128 * Hdim, A1 ? A1 + m_t * 128 * Hdim : A0 };
    const __half* Wp[2] = { W0 + (size_t)n_t * 64 * Hdim, W1 ? W1 + (size_t)n_t * 64 * Hdim : W0 };

    auto load_chunk = [&](int ch) {
        const int pass = ch >> 3, c = ch & 7;
        const uint32_t st = tb + (ch % NSTG) * STG;
        const char* ap = (const char*)Ap[pass] + c * 256;   // gmem row stride 2048B
        const char* wp = (const char*)Wp[pass] + c * 256;
#pragma unroll
        for (int i = 0; i < 4; i++) {               // A: 128 rows x 16 segs
            int idx = tid + i * NTHR;
            int row = idx >> 4, seg = idx & 15;
            cpa16(st + row * ASTR + seg * 16, ap + (size_t)row * 2048 + seg * 16);
        }
#pragma unroll
        for (int i = 0; i < 2; i++) {               // W: 64 rows x 16 segs
            int idx = tid + i * NTHR;
            int row = idx >> 4, seg = idx & 15;
            cpa16(st + OFF_B + row * ASTR + seg * 16, wp + (size_t)row * 2048 + seg * 16);
        }
        cp_commit();
    };

    const int lane = tid & 31, wrp = tid >> 5;
    const int wm = wrp & 3, wn = (wrp >> 2) & 1, kh = wrp >> 3;
    const int mat = lane >> 3, r = lane & 7;
    // lane-invariant parts of fragment addresses; kh picks the 64-k half (128B offset)
    const uint32_t a_off = (uint32_t)(wm * 32 + (mat & 1) * 8 + r) * ASTR
                         + ((mat >> 1) * 8) * 2 + kh * 128;
    const uint32_t b_off = OFF_B + (uint32_t)(wn * 32 + (mat >> 1) * 8 + r) * ASTR
                         + ((mat & 1) * 8) * 2 + kh * 128;

    float acc[2][4][4];                     // [M-frag am][gate][elem]
#pragma unroll
    for (int a = 0; a < 2; a++)
#pragma unroll
        for (int j = 0; j < 4; j++)
#pragma unroll
            for (int e = 0; e < 4; e++) acc[a][j][e] = 0.0f;

    load_chunk(0);
    load_chunk(1);
    load_chunk(2);

#pragma unroll 1
    for (int ch = 0; ch < C; ch++) {
        const int rem = C - 1 - ch;
        if (rem >= 2) cp_wait<2>(); else if (rem == 1) cp_wait<1>(); else cp_wait<0>();
        __syncthreads();                    // stage ch visible; stage (ch+3)%4 free
        if (ch + 3 < C) load_chunk(ch + 3);
        const uint32_t sa = tb + (ch % NSTG) * STG;
#pragma unroll
        for (int ks = 0; ks < 4; ks++) {    // 4 k16-steps within this warp's 64-k half
            uint32_t aF[2][4];
            ldm4(aF[0], sa + a_off + ks * 32);
            ldm4(aF[1], sa + a_off + 16 * ASTR + ks * 32);
#pragma unroll
            for (int q = 0; q < 2; q++) {
                uint32_t b4[4];
                ldm4(b4, sa + b_off + q * 16 * ASTR + ks * 32);
                mma16816(acc[0][2 * q],     aF[0], b4[0], b4[1]);
                mma16816(acc[0][2 * q + 1], aF[0], b4[2], b4[3]);
                mma16816(acc[1][2 * q],     aF[1], b4[0], b4[1]);
                mma16816(acc[1][2 * q + 1], aF[1], b4[2], b4[3]);
            }
        }
    }

    // ---- cross-K reduction: partner warps (kh=0 <-> kh=1) swap one M-frag half.
    // Warp keeps am=kh (rows wm*32+kh*16..+16) and gives away am=kh^1.
    __syncthreads();                        // all smem stage reads done; reuse as buffer
    {
        float* red = (float*)dsm;           // 8 pairs x 2 slots x 32 lanes x 16 floats = 32KB
        float* slot = red + (((wrp & 7) * 2 + kh) * 32 + lane) * 16;
        const int gv = kh ^ 1;
#pragma unroll
        for (int j = 0; j < 4; j++)
            *(float4*)(slot + j * 4) = make_float4(acc[gv][j][0], acc[gv][j][1],
                                                   acc[gv][j][2], acc[gv][j][3]);
    }
    __syncthreads();
    {
        const float* red = (const float*)dsm;
        const float* psl = red + (((wrp & 7) * 2 + (kh ^ 1)) * 32 + lane) * 16;
#pragma unroll
        for (int j = 0; j < 4; j++) {
            float4 v = *(const float4*)(psl + j * 4);
            acc[kh][j][0] += v.x; acc[kh][j][1] += v.y;
            acc[kh][j][2] += v.z; acc[kh][j][3] += v.w;
        }
    }

    // ---- epilogue: acc[kh][j] = gate j; thread owns 2 rows x 2 hids ----
    const int grp = lane >> 2, tig = lane & 3;
    const int hid0 = n_t * 16 + wn * 8 + 2 * tig;
#pragma unroll
    for (int s = 0; s < 2; s++) {
        int mm = m_t * 128 + wm * 32 + kh * 16 + grp + 8 * s;
        float xv = xs ? xs[(size_t)mm * xs_stride] : 0.0f;
        float hn[2];
#pragma unroll
        for (int d = 0; d < 2; d++) {
            int e = 2 * s + d;
            int hd = hid0 + d;
            float pi = acc[kh][0][e] + bias[hd]        + (wih ? xv * wih[hd]        : 0.f);
            float pf = acc[kh][1][e] + bias[1024 + hd] + (wih ? xv * wih[1024 + hd] : 0.f);
            float pg = acc[kh][2][e] + bias[2048 + hd] + (wih ? xv * wih[2048 + hd] : 0.f);
            float po = acc[kh][3][e] + bias[3072 + hd] + (wih ? xv * wih[3072 + hd] : 0.f);
            size_t cix = (size_t)mm * Hdim + hd;
            float cn = sigmoidf_(pf) * cst[cix] + sigmoidf_(pi) * tanhf(pg);
            hn[d] = sigmoidf_(po) * tanhf(cn);
            cst[cix] = cn;
        }
        size_t hix = (size_t)mm * Hdim + hid0;
        __half h0 = __float2half_rn(hn[0]);
        __half h1 = __float2half_rn(hn[1]);
        *(uint32_t*)&oA[hix] = (uint32_t)__half_as_ushort(h0) | ((uint32_t)__half_as_ushort(h1) << 16);
        if (of32) *(float2*)&of32[hix] = make_float2(hn[0], hn[1]);
    }
}

__device__ __forceinline__ void fc_phase(
    const float* __restrict__ h1, const float* __restrict__ fcW,
    const float* __restrict__ fcb, float* __restrict__ out, int s)
{
    if (blockIdx.x >= 16) return;           // 16 CTAs x 16 warps = 256 rows
    int warp = threadIdx.x >> 5, lane = threadIdx.x & 31;
    int b = blockIdx.x * 16 + warp;
    float sum = 0.0f;
    const float* hr = h1 + (size_t)b * Hdim;
#pragma unroll 8
    for (int k = lane; k < Hdim; k += 32) sum += hr[k] * fcW[k];
#pragma unroll
    for (int o = 16; o > 0; o >>= 1) sum += __shfl_down_sync(0xFFFFFFFFu, sum, o);
    if (lane == 0) {
        float y = sum + fcb[0];
        out[(size_t)b * OUTLEN + s] = y;
        g_xt[b] = y;
    }
}

__global__ void __launch_bounds__(NTHR, 1) lstm_mma_kernel(
    const float* __restrict__ x,
    const float* eWih0, const float* eWhh0, const float* eb0,
    const float* eWih1, const float* eWhh1, const float* eb1,
    const float* dWih0, const float* dWhh0, const float* db0,
    const float* dWih1, const float* dWhh1, const float* db1,
    const float* fcW, const float* fcb, float* __restrict__ out)
{
    extern __shared__ uint8_t dsm[];
    const uint32_t tb = smem_u32(dsm);

    const float* Ws[6] = { eWhh0, eWih1, eWhh1, dWhh0, dWih1, dWhh1 };
    prologue(Ws, x);
    grid_sync();

    int p0 = 0, p1 = 0;

#pragma unroll 1
    for (int t = 0; t < Tlen; t++) {
        lstm_phase(tb, 1,
            g_A[0][p0], g_W[0], nullptr, nullptr,
            eb0, eWih0, x + t, Tlen, g_c0,
            g_A[0][p0 ^ 1], nullptr);
        p0 ^= 1;
        grid_sync();
        lstm_phase(tb, 2,
            g_A[0][p0], g_W[1], g_A[1][p1], g_W[2],
            eb1, nullptr, nullptr, 0, g_c1,
            g_A[1][p1 ^ 1], nullptr);
        p1 ^= 1;
        grid_sync();
    }
#pragma unroll 1
    for (int s = 0; s < OUTLEN; s++) {
        lstm_phase(tb, 1,
            g_A[0][p0], g_W[3], nullptr, nullptr,
            db0, dWih0, g_xt, 1, g_c0,
            g_A[0][p0 ^ 1], nullptr);
        p0 ^= 1;
        grid_sync();
        lstm_phase(tb, 2,
            g_A[0][p0], g_W[4], g_A[1][p1], g_W[5],
            db1, nullptr, nullptr, 0, g_c1,
            g_A[1][p1 ^ 1], g_h1f);
        p1 ^= 1;
        grid_sync();
        fc_phase(g_h1f, fcW, fcb, out, s);
        grid_sync();
    }
}

extern "C" void kernel_launch(void* const* d_in, const int* in_sizes, int n_in,
                              void* d_out, int out_size)
{
    (void)in_sizes; (void)n_in; (void)out_size;
    cudaFuncSetAttribute(lstm_mma_kernel, cudaFuncAttributeMaxDynamicSharedMemorySize, SMEM_TOTAL);
    lstm_mma_kernel<<<NCTA, NTHR, SMEM_TOTAL>>>(
        (const float*)d_in[0],
        (const float*)d_in[1],  (const float*)d_in[2],  (const float*)d_in[3],
        (const float*)d_in[4],  (const float*)d_in[5],  (const float*)d_in[6],
        (const float*)d_in[7],  (const float*)d_in[8],  (const float*)d_in[9],
        (const float*)d_in[10], (const float*)d_in[11], (const float*)d_in[12],
        (const float*)d_in[13], (const float*)d_in[14],
        (float*)d_out);
}

// round 14
// speedup vs baseline: 1.3134x; 1.2643x over previous
#include <cuda_runtime.h>
#include <cuda_fp16.h>
#include <cstdint>
#include <cstddef>

// Persistent 1-term fp16 HMMA LSTM. 128 CTAs x 512 threads, warp tile 16x32 (R11).
// R14: staging via cp.async.bulk (2 bulk copies/chunk, mbarrier complete_tx)
// from pre-swizzled chunk-contiguous gmem images. Kills the cp.async LSU
// issue floor (3072 ops/chunk -> ~4) identified as the R8-R13 bottleneck.
#define Bsz 256
#define Hdim 1024
#define Tlen 336
#define OUTLEN 96
#define BH (Bsz*Hdim)
#define NCTA 128
#define NTHR 512
#define STG 49152                 // stage: A 32KB (128x256B) + W 16KB (64x256B)
#define OFF_W 32768
#define NSTG 4
#define MB_OFF (NSTG*STG)         // 4 mbarriers (8B each)
#define SMEM_TOTAL (NSTG*STG + 64)

// Pre-swizzled images. A: [chunk 8][m 256][256B]; W: [ntile 64][chunk 8][row 64][256B].
__device__ __align__(128) uint8_t g_Aimg[2][2][524288];     // [layer][ping]
__device__ __align__(128) uint8_t g_Wimg[6][8388608];
__device__ float g_c0[BH], g_c1[BH], g_h1f[BH], g_xt[Bsz];
__device__ unsigned g_cnt, g_gen;

__device__ __forceinline__ uint32_t smem_u32(const void* p) {
    uint32_t a;
    asm("{ .reg .u64 t; cvta.to.shared.u64 t, %1; cvt.u32.u64 %0, t; }" : "=r"(a) : "l"(p));
    return a;
}
__device__ __forceinline__ void bulk_g2s(uint32_t dst, const void* src, uint32_t bytes, uint32_t mbar) {
    asm volatile(
        "cp.async.bulk.shared::cluster.global.mbarrier::complete_tx::bytes [%0], [%1], %2, [%3];"
        :: "r"(dst), "l"(src), "r"(bytes), "r"(mbar) : "memory");
}
__device__ __forceinline__ void mbar_init(uint32_t a, uint32_t c) {
    asm volatile("mbarrier.init.shared.b64 [%0], %1;" :: "r"(a), "r"(c) : "memory");
}
__device__ __forceinline__ void mbar_expect_tx(uint32_t a, uint32_t bytes) {
    asm volatile("mbarrier.arrive.expect_tx.shared.b64 _, [%0], %1;" :: "r"(a), "r"(bytes) : "memory");
}
__device__ __forceinline__ void mbar_wait(uint32_t a, uint32_t par) {
    uint32_t done;
    asm volatile("{\n\t.reg .pred p;\n\t"
        "mbarrier.try_wait.parity.acquire.cta.shared::cta.b64 p, [%1], %2;\n\t"
        "selp.b32 %0, 1, 0, p;\n\t}" : "=r"(done) : "r"(a), "r"(par) : "memory");
    if (!done) {
        asm volatile("{\n\t.reg .pred P1;\n\tW_%=:\n\t"
            "mbarrier.try_wait.parity.acquire.cta.shared::cta.b64 P1, [%0], %1, 0x989680;\n\t"
            "@P1 bra.uni D_%=;\n\tbra.uni W_%=;\n\tD_%=:\n\t}" :: "r"(a), "r"(par) : "memory");
    }
}
__device__ __forceinline__ void ldm4(uint32_t* r, uint32_t a) {
    asm volatile("ldmatrix.sync.aligned.m8n8.x4.shared.b16 {%0,%1,%2,%3}, [%4];"
        : "=r"(r[0]), "=r"(r[1]), "=r"(r[2]), "=r"(r[3]) : "r"(a));
}
__device__ __forceinline__ void mma16816(float* c, const uint32_t* a, uint32_t b0, uint32_t b1) {
    asm volatile(
        "mma.sync.aligned.m16n8k16.row.col.f32.f16.f16.f32 "
        "{%0,%1,%2,%3}, {%4,%5,%6,%7}, {%8,%9}, {%0,%1,%2,%3};"
        : "+f"(c[0]), "+f"(c[1]), "+f"(c[2]), "+f"(c[3])
        : "r"(a[0]), "r"(a[1]), "r"(a[2]), "r"(a[3]), "r"(b0), "r"(b1));
}
__device__ __forceinline__ float sigmoidf_(float x) { return 1.0f / (1.0f + expf(-x)); }

__device__ __forceinline__ void grid_sync() {
    __syncthreads();
    if (threadIdx.x == 0) {
        __threadfence();
        unsigned g = *(volatile unsigned*)&g_gen;
        unsigned a = atomicAdd(&g_cnt, 1u);
        if (a == NCTA - 1) {
            atomicExch(&g_cnt, 0u);
            __threadfence();
            atomicAdd(&g_gen, 1u);
        } else {
            while (*(volatile unsigned*)&g_gen == g) { __nanosleep(64); }
        }
        __threadfence();
    }
    __syncthreads();
}

// SW128-style XOR on the 16B segment index within a 256B row.
__device__ __forceinline__ uint32_t physseg(uint32_t seg, uint32_t row) {
    return (seg & 8u) | ((seg & 7u) ^ (row & 7u));
}

// Weights -> swizzled images. col = (hid>>4)*64 + ((hid>>3)&1)*32 + gate*8 + (hid&7).
__device__ void prologue(const float* const* Ws, const float* x) {
    const int gt = blockIdx.x * NTHR + threadIdx.x;
#pragma unroll 1
    for (int mat = 0; mat < 6; mat++) {
        const float* src = Ws[mat];
#pragma unroll 1
        for (int p = gt; p < (4096 * 1024 / 2); p += NCTA * NTHR) {
            int gr = p >> 9;
            int k  = (p & 511) << 1;
            float2 v = *(const float2*)(src + (size_t)gr * 1024 + k);
            int gate = gr >> 10, hid = gr & 1023;
            int col = (hid >> 4) * 64 + ((hid >> 3) & 1) * 32 + gate * 8 + (hid & 7);
            uint32_t nt = (uint32_t)col >> 6, r = (uint32_t)col & 63;
            uint32_t c = (uint32_t)k >> 7, koff = (uint32_t)k & 127;
            size_t off = (size_t)(((nt << 3) + c) << 14) + r * 256
                       + physseg(koff >> 3, r) * 16 + (koff & 7) * 2;
            __half h0 = __float2half_rn(v.x);
            __half h1 = __float2half_rn(v.y);
            *(uint32_t*)&g_Wimg[mat][off] =
                (uint32_t)__half_as_ushort(h0) | ((uint32_t)__half_as_ushort(h1) << 16);
        }
    }
    float4 zf = make_float4(0.f, 0.f, 0.f, 0.f);
    uint4 z4 = make_uint4(0, 0, 0, 0);
    for (int i = gt; i < BH / 4; i += NCTA * NTHR) {
        ((float4*)g_c0)[i] = zf;
        ((float4*)g_c1)[i] = zf;
    }
    for (int i = gt; i < 524288 / 16; i += NCTA * NTHR) {
        ((uint4*)g_Aimg[0][0])[i] = z4;
        ((uint4*)g_Aimg[1][0])[i] = z4;
    }
    if (gt < Bsz) g_xt[gt] = x[(size_t)gt * Tlen + (Tlen - 1)];
}

// One recurrence phase: D(128x64) = sum over passes A@W^T, fused LSTM pointwise.
__device__ __noinline__ void lstm_phase(
    uint32_t tb, int npass,
    const uint8_t* A0, const uint8_t* W0,
    const uint8_t* A1, const uint8_t* W1,
    const float* __restrict__ bias, const float* __restrict__ wih,
    const float* __restrict__ xs, int xs_stride,
    float* __restrict__ cst,
    uint8_t* __restrict__ oA, float* __restrict__ of32, int* par)
{
    const int tid = threadIdx.x;
    const int m_t = blockIdx.x & 1;
    const int n_t = blockIdx.x >> 1;
    const int C = npass << 3;               // 8 chunks of K=128 per pass
    const uint32_t mb = tb + MB_OFF;

    auto prefetch = [&](int j) {            // tid 0 only
        const int pass = j >> 3, c = j & 7;
        const int s = j & 3;
        const uint8_t* ai = pass ? A1 : A0;
        const uint8_t* wi = pass ? W1 : W0;
        mbar_expect_tx(mb + s * 8, STG);
        bulk_g2s(tb + s * STG, ai + (size_t)((c * 256 + m_t * 128) << 8), 32768, mb + s * 8);
        bulk_g2s(tb + s * STG + OFF_W, wi + (size_t)(((n_t << 3) + c) << 14), 16384, mb + s * 8);
    };

    const int lane = tid & 31, w = tid >> 5;
    const int wm = w & 7, wn = w >> 3;
    const int mat = lane >> 3, rr = lane & 7;
    const uint32_t aRow = wm * 16 + (mat & 1) * 8 + rr;
    const uint32_t aSeg0 = (uint32_t)(mat >> 1);
    const uint32_t aXor = aRow & 7;
    const uint32_t bRow = wn * 32 + (mat >> 1) * 8 + rr;    // + q*16 (low 3 bits same)
    const uint32_t bSeg0 = (uint32_t)(mat & 1);
    const uint32_t bXor = bRow & 7;

    float acc[4][4];
#pragma unroll
    for (int j = 0; j < 4; j++)
#pragma unroll
        for (int e = 0; e < 4; e++) acc[j][e] = 0.0f;

    if (tid == 0) { prefetch(0); prefetch(1); prefetch(2); }

#pragma unroll 1
    for (int ch = 0; ch < C; ch++) {
        __syncthreads();                    // prior chunk fully read -> stage free
        if (tid == 0 && ch + 3 < C) prefetch(ch + 3);
        const int s = ch & 3;
        mbar_wait(mb + s * 8, (uint32_t)(par[s] & 1));
        par[s]++;
        const uint32_t sa = tb + s * STG;
#pragma unroll
        for (int ks = 0; ks < 8; ks++) {
            uint32_t a4[4];
            uint32_t segA = (uint32_t)(ks * 2) + aSeg0;
            ldm4(a4, sa + aRow * 256 + physseg(segA, aXor) * 16);
#pragma unroll
            for (int q = 0; q < 2; q++) {
                uint32_t b4[4];
                uint32_t segB = (uint32_t)(ks * 2) + bSeg0;
                ldm4(b4, sa + OFF_W + (bRow + q * 16) * 256 + physseg(segB, bXor) * 16);
                mma16816(acc[2 * q],     a4, b4[0], b4[1]);
                mma16816(acc[2 * q + 1], a4, b4[2], b4[3]);
            }
        }
    }

    // ---- epilogue: acc[j] = gate j; thread owns 2 rows x 2 hids ----
    const int grp = lane >> 2, tig = lane & 3;
    const int hid0 = n_t * 16 + wn * 8 + 2 * tig;
#pragma unroll
    for (int s = 0; s < 2; s++) {
        int mm = m_t * 128 + wm * 16 + grp + 8 * s;
        float xv = xs ? xs[(size_t)mm * xs_stride] : 0.0f;
        float hn[2];
#pragma unroll
        for (int d = 0; d < 2; d++) {
            int e = 2 * s + d;
            int hd = hid0 + d;
            float pi = acc[0][e] + bias[hd]        + (wih ? xv * wih[hd]        : 0.f);
            float pf = acc[1][e] + bias[1024 + hd] + (wih ? xv * wih[1024 + hd] : 0.f);
            float pg = acc[2][e] + bias[2048 + hd] + (wih ? xv * wih[2048 + hd] : 0.f);
            float po = acc[3][e] + bias[3072 + hd] + (wih ? xv * wih[3072 + hd] : 0.f);
            size_t cix = (size_t)mm * Hdim + hd;
            float cn = sigmoidf_(pf) * cst[cix] + sigmoidf_(pi) * tanhf(pg);
            hn[d] = sigmoidf_(po) * tanhf(cn);
            cst[cix] = cn;
        }
        // write into swizzled A image: [chunk][m 0..255][256B]
        uint32_t c = (uint32_t)hid0 >> 7, koff = (uint32_t)hid0 & 127;
        size_t aoff = (size_t)((c * 256 + (uint32_t)mm) << 8)
                    + physseg(koff >> 3, (uint32_t)mm) * 16 + (koff & 7) * 2;
        __half h0 = __float2half_rn(hn[0]);
        __half h1 = __float2half_rn(hn[1]);
        *(uint32_t*)&oA[aoff] =
            (uint32_t)__half_as_ushort(h0) | ((uint32_t)__half_as_ushort(h1) << 16);
        if (of32) *(float2*)&of32[(size_t)mm * Hdim + hid0] = make_float2(hn[0], hn[1]);
    }
}

__device__ __forceinline__ void fc_phase(
    const float* __restrict__ h1, const float* __restrict__ fcW,
    const float* __restrict__ fcb, float* __restrict__ out, int s)
{
    if (blockIdx.x >= 16) return;           // 16 CTAs x 16 warps = 256 rows
    int warp = threadIdx.x >> 5, lane = threadIdx.x & 31;
    int b = blockIdx.x * 16 + warp;
    float sum = 0.0f;
    const float* hr = h1 + (size_t)b * Hdim;
#pragma unroll 8
    for (int k = lane; k < Hdim; k += 32) sum += hr[k] * fcW[k];
#pragma unroll
    for (int o = 16; o > 0; o >>= 1) sum += __shfl_down_sync(0xFFFFFFFFu, sum, o);
    if (lane == 0) {
        float y = sum + fcb[0];
        out[(size_t)b * OUTLEN + s] = y;
        g_xt[b] = y;
    }
}

__global__ void __launch_bounds__(NTHR, 1) lstm_mma_kernel(
    const float* __restrict__ x,
    const float* eWih0, const float* eWhh0, const float* eb0,
    const float* eWih1, const float* eWhh1, const float* eb1,
    const float* dWih0, const float* dWhh0, const float* db0,
    const float* dWih1, const float* dWhh1, const float* db1,
    const float* fcW, const float* fcb, float* __restrict__ out)
{
    extern __shared__ uint8_t dsm[];
    const uint32_t tb = smem_u32(dsm);

    if (threadIdx.x == 0) {
        mbar_init(tb + MB_OFF + 0, 1);
        mbar_init(tb + MB_OFF + 8, 1);
        mbar_init(tb + MB_OFF + 16, 1);
        mbar_init(tb + MB_OFF + 24, 1);
    }
    const float* Ws[6] = { eWhh0, eWih1, eWhh1, dWhh0, dWih1, dWhh1 };
    prologue(Ws, x);
    grid_sync();                            // also publishes mbarrier init

    int par[NSTG] = { 0, 0, 0, 0 };
    int p0 = 0, p1 = 0;

#pragma unroll 1
    for (int t = 0; t < Tlen; t++) {
        lstm_phase(tb, 1,
            g_Aimg[0][p0], g_Wimg[0], nullptr, nullptr,
            eb0, eWih0, x + t, Tlen, g_c0,
            g_Aimg[0][p0 ^ 1], nullptr, par);
        p0 ^= 1;
        grid_sync();
        lstm_phase(tb, 2,
            g_Aimg[0][p0], g_Wimg[1], g_Aimg[1][p1], g_Wimg[2],
            eb1, nullptr, nullptr, 0, g_c1,
            g_Aimg[1][p1 ^ 1], nullptr, par);
        p1 ^= 1;
        grid_sync();
    }
#pragma unroll 1
    for (int s = 0; s < OUTLEN; s++) {
        lstm_phase(tb, 1,
            g_Aimg[0][p0], g_Wimg[3], nullptr, nullptr,
            db0, dWih0, g_xt, 1, g_c0,
            g_Aimg[0][p0 ^ 1], nullptr, par);
        p0 ^= 1;
        grid_sync();
        lstm_phase(tb, 2,
            g_Aimg[0][p0], g_Wimg[4], g_Aimg[1][p1], g_Wimg[5],
            db1, nullptr, nullptr, 0, g_c1,
            g_Aimg[1][p1 ^ 1], g_h1f, par);
        p1 ^= 1;
        grid_sync();
        fc_phase(g_h1f, fcW, fcb, out, s);
        grid_sync();
    }
}

extern "C" void kernel_launch(void* const* d_in, const int* in_sizes, int n_in,
                              void* d_out, int out_size)
{
    (void)in_sizes; (void)n_in; (void)out_size;
    cudaFuncSetAttribute(lstm_mma_kernel, cudaFuncAttributeMaxDynamicSharedMemorySize, SMEM_TOTAL);
    lstm_mma_kernel<<<NCTA, NTHR, SMEM_TOTAL>>>(
        (const float*)d_in[0],
        (const float*)d_in[1],  (const float*)d_in[2],  (const float*)d_in[3],
        (const float*)d_in[4],  (const float*)d_in[5],  (const float*)d_in[6],
        (const float*)d_in[7],  (const float*)d_in[8],  (const float*)d_in[9],
        (const float*)d_in[10], (const float*)d_in[11], (const float*)d_in[12],
        (const float*)d_in[13], (const float*)d_in[14],
        (float*)d_out);
}